// round 6
// baseline (speedup 1.0000x reference)
#include <cuda_runtime.h>
#include <math.h>

// SimilarityTreeLSTM on GB300: level-parallel tree evaluation in one
// persistent kernel with a software grid barrier.
//
// R5 changes vs R4:
//  * packed f32x2 FMA (fma.rn.f32x2) pairing adjacent nodes per 64-bit lane
//    -> 2 MACs per FMA-pipe issue (ptxas never emits this from C++)
//  * pair-interleaved smem h layout: one broadcast LDS.64 = one packed operand
//  * adaptive group width NT in {16,4,2} per level: dense levels keep 16x
//    weight reuse, sparse levels get 8x cheaper groups + full-grid occupancy

#define NNODE 65536
#define TOT   (2 * NNODE)
#define M     256
#define M3    (3 * M)
#define VOCAB 1000
#define VNB   8
#define MAXD_CAP 65536

typedef unsigned long long u64;

// ---------------- device scratch (static: no allocations allowed) ----------
__device__ float g_hsum[TOT * M];        // 134 MB
__device__ float g_fcsum[TOT * M];       // 134 MB
__device__ float g_ioux[VOCAB * M3];     // vocab proj: emb@Wioux + bioux
__device__ float g_fxp[VOCAB * M];       // vocab proj: emb@Wfx + bfx
__device__ int   g_depth[TOT];
__device__ int   g_order[TOT];
__device__ int   g_hist[MAXD_CAP];
__device__ int   g_startv[MAXD_CAP];
__device__ int   g_cursor[MAXD_CAP];
__device__ int   g_maxd;
__device__ float g_croot[2 * M];
__device__ unsigned g_barcnt;
__device__ unsigned g_sense;

__device__ __forceinline__ float sigf(float x) {
    return 1.0f / (1.0f + expf(-x));
}

// packed f32x2 helpers
__device__ __forceinline__ u64 rep2(float v) {
    u64 r; asm("mov.b64 %0, {%1, %1};" : "=l"(r) : "f"(v)); return r;
}
__device__ __forceinline__ u64 pk2(float lo, float hi) {
    u64 r; asm("mov.b64 %0, {%1, %2};" : "=l"(r) : "f"(lo), "f"(hi)); return r;
}
__device__ __forceinline__ float2 upk(u64 v) {
    float2 f; asm("mov.b64 {%0, %1}, %2;" : "=f"(f.x), "=f"(f.y) : "l"(v)); return f;
}
#define FMA2(acc, x, y) asm("fma.rn.f32x2 %0, %1, %2, %0;" : "+l"(acc) : "l"(x), "l"(y))

// Sense-reversal grid barrier. Requires all blocks co-resident.
__device__ __forceinline__ void gsync() {
    __syncthreads();
    if (threadIdx.x == 0) {
        __threadfence();
        unsigned target = *((volatile unsigned*)&g_sense) + 1u;
        unsigned a = atomicAdd(&g_barcnt, 1u);
        if (a == gridDim.x - 1u) {
            g_barcnt = 0u;
            __threadfence();
            atomicExch(&g_sense, target);
        } else {
            while (*((volatile unsigned*)&g_sense) != target) { __nanosleep(64); }
        }
        __threadfence();
    }
    __syncthreads();
}

// Process one tree level with NT nodes per block-group.
// s_hf layout: pair-interleaved, float index k*NT + n  (n = node slot).
template <int NT>
__device__ void do_level(int s0, int cnt,
                         const int* __restrict__ l_tok, const int* __restrict__ l_par,
                         const int* __restrict__ r_tok, const int* __restrict__ r_par,
                         const float* __restrict__ Wiouh, const float* __restrict__ Wfh,
                         float bio0, float bio1, float bio2, float bfh_t,
                         float* s_hf, int* s_node, int* s_tok, int* s_parg, int* s_ptok)
{
    constexpr int P = NT / 2;
    const int t = threadIdx.x;
    const int ngrp = (cnt + NT - 1) / NT;

    for (int g = blockIdx.x; g < ngrp; g += gridDim.x) {
        const int base = s0 + g * NT;
        const int nn   = min(NT, cnt - g * NT);
        if (t < NT) {
            int idx  = base + ((t < nn) ? t : 0);    // clamp (dup node 0 of grp)
            int node = g_order[idx];
            int tree = node >> 16, loc = node & (NNODE - 1);
            const int* tokp = tree ? r_tok : l_tok;
            const int* parp = tree ? r_par : l_par;
            int pl = parp[loc];
            s_node[t] = node;
            s_tok[t]  = tokp[loc];
            s_parg[t] = (tree << 16) + pl;
            s_ptok[t] = tokp[pl];
        }
        __syncthreads();
        // load h_sum rows, pair-interleaved (bypass L1: updated via L2 atomics)
        #pragma unroll
        for (int p = 0; p < P; p++) {
            float x = __ldcg(&g_hsum[s_node[2 * p] * M + t]);
            float y = __ldcg(&g_hsum[s_node[2 * p + 1] * M + t]);
            *reinterpret_cast<u64*>(s_hf + t * NT + 2 * p) = pk2(x, y);
        }
        __syncthreads();

        u64 a0[P], a1[P], a2[P];
        #pragma unroll
        for (int p = 0; p < P; p++) {
            int tx = s_tok[2 * p], ty = s_tok[2 * p + 1];
            a0[p] = pk2(g_ioux[tx * M3 + t] + bio0,         g_ioux[ty * M3 + t] + bio0);
            a1[p] = pk2(g_ioux[tx * M3 + M + t] + bio1,     g_ioux[ty * M3 + M + t] + bio1);
            a2[p] = pk2(g_ioux[tx * M3 + 2 * M + t] + bio2, g_ioux[ty * M3 + 2 * M + t] + bio2);
        }

        // ---- Wiouh matvec: packed FMA2, 2-step weight double-buffer ----
        {
            float wA0 = Wiouh[t], wA1 = Wiouh[M + t], wA2 = Wiouh[2 * M + t];
            #pragma unroll 1
            for (int k = 0; k < M; k += 2) {
                float wB0 = Wiouh[(k + 1) * M3 + t];
                float wB1 = Wiouh[(k + 1) * M3 + M + t];
                float wB2 = Wiouh[(k + 1) * M3 + 2 * M + t];
                u64 w0 = rep2(wA0), w1 = rep2(wA1), w2 = rep2(wA2);
                const u64* hk = reinterpret_cast<const u64*>(s_hf + k * NT);
                #pragma unroll
                for (int p = 0; p < P; p++) {
                    u64 hp = hk[p];
                    FMA2(a0[p], hp, w0); FMA2(a1[p], hp, w1); FMA2(a2[p], hp, w2);
                }
                if (k + 2 < M) {
                    wA0 = Wiouh[(k + 2) * M3 + t];
                    wA1 = Wiouh[(k + 2) * M3 + M + t];
                    wA2 = Wiouh[(k + 2) * M3 + 2 * M + t];
                }
                w0 = rep2(wB0); w1 = rep2(wB1); w2 = rep2(wB2);
                const u64* hk1 = reinterpret_cast<const u64*>(s_hf + (k + 1) * NT);
                #pragma unroll
                for (int p = 0; p < P; p++) {
                    u64 hp = hk1[p];
                    FMA2(a0[p], hp, w0); FMA2(a1[p], hp, w1); FMA2(a2[p], hp, w2);
                }
            }
        }

        float cv[NT], hv[NT];
        #pragma unroll
        for (int p = 0; p < P; p++) {
            float2 f0 = upk(a0[p]), f1 = upk(a1[p]), f2 = upk(a2[p]);
            float fcx = __ldcg(&g_fcsum[s_node[2 * p] * M + t]);
            float cx  = sigf(f0.x) * tanhf(f2.x) + fcx;
            cv[2 * p] = cx;  hv[2 * p] = sigf(f1.x) * tanhf(cx);
            float fcy = __ldcg(&g_fcsum[s_node[2 * p + 1] * M + t]);
            float cy  = sigf(f0.y) * tanhf(f2.y) + fcy;
            cv[2 * p + 1] = cy;  hv[2 * p + 1] = sigf(f1.y) * tanhf(cy);
        }
        __syncthreads();                 // done reading s_hf as h_sum
        #pragma unroll
        for (int p = 0; p < P; p++)
            *reinterpret_cast<u64*>(s_hf + t * NT + 2 * p) = pk2(hv[2 * p], hv[2 * p + 1]);
        __syncthreads();

        u64 b[P];
        #pragma unroll
        for (int p = 0; p < P; p++)
            b[p] = pk2(bfh_t + g_fxp[s_ptok[2 * p] * M + t],
                       bfh_t + g_fxp[s_ptok[2 * p + 1] * M + t]);

        // ---- Wfh matvec: packed FMA2, 2-step weight double-buffer ----
        {
            float wA = Wfh[t];
            #pragma unroll 1
            for (int k = 0; k < M; k += 2) {
                float wB = Wfh[(k + 1) * M + t];
                u64 w = rep2(wA);
                const u64* hk = reinterpret_cast<const u64*>(s_hf + k * NT);
                #pragma unroll
                for (int p = 0; p < P; p++) { FMA2(b[p], hk[p], w); }
                if (k + 2 < M) wA = Wfh[(k + 2) * M + t];
                w = rep2(wB);
                const u64* hk1 = reinterpret_cast<const u64*>(s_hf + (k + 1) * NT);
                #pragma unroll
                for (int p = 0; p < P; p++) { FMA2(b[p], hk1[p], w); }
            }
        }

        #pragma unroll
        for (int n = 0; n < NT; n++) {
            if (n < nn) {
                int node = s_node[n];
                float2 bf = upk(b[n / 2]);
                float bb = (n & 1) ? bf.y : bf.x;
                if (node & (NNODE - 1)) {        // not a root
                    float f = sigf(bb);
                    atomicAdd(&g_hsum[s_parg[n] * M + t], hv[n]);
                    atomicAdd(&g_fcsum[s_parg[n] * M + t], f * cv[n]);
                } else {
                    g_croot[(node >> 16) * M + t] = cv[n];
                }
            }
        }
        __syncthreads();
    }
}

extern "C" __global__ void __launch_bounds__(256, 2)
treelstm_kernel(const int* __restrict__ l_tok, const int* __restrict__ l_par,
                const int* __restrict__ r_tok, const int* __restrict__ r_par,
                const float* __restrict__ emb,
                const float* __restrict__ Wioux, const float* __restrict__ bioux,
                const float* __restrict__ Wiouh, const float* __restrict__ biouh,
                const float* __restrict__ Wfx,   const float* __restrict__ bfx,
                const float* __restrict__ Wfh,   const float* __restrict__ bfh,
                const float* __restrict__ Wh,    const float* __restrict__ bh,
                const float* __restrict__ Wp,    const float* __restrict__ bp,
                float* __restrict__ out)
{
    __shared__ __align__(16) float s_hf[16 * M];   // 16 KB, multi-purpose
    __shared__ int s_node[16], s_tok[16], s_parg[16], s_ptok[16];

    const int t   = threadIdx.x;
    const int gid = blockIdx.x * blockDim.x + threadIdx.x;
    const int gs  = gridDim.x * blockDim.x;

    // ---------------- Phase 0: zero state + vocab projections ------------
    {
        float4 z4 = make_float4(0.f, 0.f, 0.f, 0.f);
        float4* h4p = reinterpret_cast<float4*>(g_hsum);
        float4* f4p = reinterpret_cast<float4*>(g_fcsum);
        const int n4 = TOT * M / 4;
        for (int i = gid; i < n4; i += gs) h4p[i] = z4;
        for (int i = gid; i < n4; i += gs) f4p[i] = z4;
        for (int i = gid; i < MAXD_CAP; i += gs) g_hist[i] = 0;
        if (gid == 0) g_maxd = 0;

        // vocab projections: groups of VNB vocab rows per block
        const int VG = VOCAB / VNB;   // 125
        for (int g = blockIdx.x; g < VG; g += gridDim.x) {
            #pragma unroll
            for (int n = 0; n < VNB; n++)
                s_hf[n * M + t] = emb[(g * VNB + n) * M + t];
            __syncthreads();
            float a0[VNB], a1[VNB], a2[VNB], af[VNB];
            #pragma unroll
            for (int n = 0; n < VNB; n++) {
                a0[n] = bioux[t]; a1[n] = bioux[M + t];
                a2[n] = bioux[2 * M + t]; af[n] = bfx[t];
            }
            #pragma unroll 1
            for (int k = 0; k < M; k += 4) {
                #pragma unroll
                for (int kk = 0; kk < 4; kk++) {
                    float w0 = Wioux[(k + kk) * M3 + t];
                    float w1 = Wioux[(k + kk) * M3 + M + t];
                    float w2 = Wioux[(k + kk) * M3 + 2 * M + t];
                    float wf = Wfx[(k + kk) * M + t];
                    #pragma unroll
                    for (int n = 0; n < VNB; n++) {
                        float xv = s_hf[n * M + k + kk];
                        a0[n] += xv * w0; a1[n] += xv * w1;
                        a2[n] += xv * w2; af[n] += xv * wf;
                    }
                }
            }
            #pragma unroll
            for (int n = 0; n < VNB; n++) {
                int v = g * VNB + n;
                g_ioux[v * M3 + t]         = a0[n];
                g_ioux[v * M3 + M + t]     = a1[n];
                g_ioux[v * M3 + 2 * M + t] = a2[n];
                g_fxp[v * M + t]           = af[n];
            }
            __syncthreads();
        }
    }
    gsync();

    // ---------------- Phase 1: depth walk + histogram ---------------------
    for (int i = gid; i < TOT; i += gs) {
        int tree = i >> 16, loc = i & (NNODE - 1);
        const int* parp = tree ? r_par : l_par;
        int d = 0, j = loc;
        while (j) { j = __ldg(parp + j); d++; }
        g_depth[i] = d;
        atomicAdd(&g_hist[d], 1);
        atomicMax(&g_maxd, d);
    }
    gsync();

    // ---------------- Phase 2: serial scan of level offsets --------------
    if (blockIdx.x == 0 && threadIdx.x == 0) {
        int s = 0, md = __ldcg(&g_maxd);
        for (int d = 0; d <= md; d++) {
            g_startv[d] = s; g_cursor[d] = s;
            s += __ldcg(&g_hist[d]);
        }
    }
    gsync();

    // ---------------- Phase 3: scatter nodes into level buckets ----------
    for (int i = gid; i < TOT; i += gs) {
        int d = g_depth[i];
        int pos = atomicAdd(&g_cursor[d], 1);
        g_order[pos] = i;
    }
    gsync();

    // loop-invariant biases
    const float bio0 = biouh[t], bio1 = biouh[M + t], bio2 = biouh[2 * M + t];
    const float bfh_t = bfh[t];

    // ---------------- Phase 4: level loop (deepest first) -----------------
    const int maxd = __ldcg(&g_maxd);
    const int G = gridDim.x;
    for (int d = maxd; d >= 0; --d) {
        const int s0  = __ldcg(&g_startv[d]);
        const int cnt = __ldcg(&g_hist[d]);
        // pick NT minimizing waves(NT)*NT (per-group time ~ NT)
        const int w16 = (int)((((cnt + 15) / 16 + G - 1) / G) * 16);
        const int w4  = (int)((((cnt + 3) / 4 + G - 1) / G) * 4);
        const int w2  = (int)((((cnt + 1) / 2 + G - 1) / G) * 2);
        if (w16 <= w4 && w16 <= w2)
            do_level<16>(s0, cnt, l_tok, l_par, r_tok, r_par, Wiouh, Wfh,
                         bio0, bio1, bio2, bfh_t, s_hf, s_node, s_tok, s_parg, s_ptok);
        else if (w4 <= w2)
            do_level<4>(s0, cnt, l_tok, l_par, r_tok, r_par, Wiouh, Wfh,
                        bio0, bio1, bio2, bfh_t, s_hf, s_node, s_tok, s_parg, s_ptok);
        else
            do_level<2>(s0, cnt, l_tok, l_par, r_tok, r_par, Wiouh, Wfh,
                        bio0, bio1, bio2, bfh_t, s_hf, s_node, s_tok, s_parg, s_ptok);
        gsync();
    }

    // ---------------- Phase 5: similarity head (block 0) ------------------
    if (blockIdx.x == 0) {
        float cl = __ldcg(&g_croot[t]);
        float cr = __ldcg(&g_croot[M + t]);
        s_hf[t]     = cl * cr;
        s_hf[M + t] = fabsf(cl - cr);
        __syncthreads();
        float acc = bh[t];
        for (int k = 0; k < 2 * M; k++) acc += s_hf[k] * Wh[k * M + t];
        float hid = sigf(acc);
        s_hf[2 * M + t] = hid * Wp[2 * t];
        s_hf[3 * M + t] = hid * Wp[2 * t + 1];
        __syncthreads();
        if (t == 0) {
            float l0 = bp[0], l1 = bp[1];
            for (int k = 0; k < M; k++) { l0 += s_hf[2 * M + k]; l1 += s_hf[3 * M + k]; }
            float mx = fmaxf(l0, l1);
            float e0 = expf(l0 - mx), e1 = expf(l1 - mx);
            float inv = 1.0f / (e0 + e1);
            out[0] = e0 * inv;
            out[1] = e1 * inv;
        }
    }
}

extern "C" void kernel_launch(void* const* d_in, const int* in_sizes, int n_in,
                              void* d_out, int out_size)
{
    (void)in_sizes; (void)n_in; (void)out_size;
    int dev = 0;
    cudaGetDevice(&dev);
    int nsm = 0;
    cudaDeviceGetAttribute(&nsm, cudaDevAttrMultiProcessorCount, dev);
    if (nsm <= 0) nsm = 148;

    treelstm_kernel<<<2 * nsm, 256>>>(
        (const int*)d_in[0], (const int*)d_in[1],
        (const int*)d_in[2], (const int*)d_in[3],
        (const float*)d_in[4],
        (const float*)d_in[5], (const float*)d_in[6],
        (const float*)d_in[7], (const float*)d_in[8],
        (const float*)d_in[9], (const float*)d_in[10],
        (const float*)d_in[11], (const float*)d_in[12],
        (const float*)d_in[13], (const float*)d_in[14],
        (const float*)d_in[15], (const float*)d_in[16],
        (float*)d_out);
}

// round 7
// speedup vs baseline: 2.0532x; 2.0532x over previous
#include <cuda_runtime.h>
#include <math.h>

// SimilarityTreeLSTM on GB300: level-parallel tree evaluation in one
// persistent kernel with a software grid barrier.
//
// R6: revert R5's f32x2 experiment (packing tax + asm scheduling fences
// regressed it). Base = R4 scalar kernel (3249us), plus:
//  * adaptive group width NT in {16,8,4} per level, cost model
//    waves(NT)*(NT+3): dense levels keep 16x weight reuse, sparse deep
//    levels get ~4x cheaper groups so the serial tail shrinks.

#define NNODE 65536
#define TOT   (2 * NNODE)
#define M     256
#define M3    (3 * M)
#define VOCAB 1000
#define VNB   8
#define MAXD_CAP 65536

// ---------------- device scratch (static: no allocations allowed) ----------
__device__ float g_hsum[TOT * M];        // 134 MB
__device__ float g_fcsum[TOT * M];       // 134 MB
__device__ float g_ioux[VOCAB * M3];     // vocab proj: emb@Wioux + bioux
__device__ float g_fxp[VOCAB * M];       // vocab proj: emb@Wfx + bfx
__device__ int   g_depth[TOT];
__device__ int   g_order[TOT];
__device__ int   g_hist[MAXD_CAP];
__device__ int   g_startv[MAXD_CAP];
__device__ int   g_cursor[MAXD_CAP];
__device__ int   g_maxd;
__device__ float g_croot[2 * M];
__device__ unsigned g_barcnt;
__device__ unsigned g_sense;

__device__ __forceinline__ float sigf(float x) {
    return 1.0f / (1.0f + expf(-x));
}

// Sense-reversal grid barrier. Requires all blocks co-resident.
__device__ __forceinline__ void gsync() {
    __syncthreads();
    if (threadIdx.x == 0) {
        __threadfence();
        unsigned target = *((volatile unsigned*)&g_sense) + 1u;
        unsigned a = atomicAdd(&g_barcnt, 1u);
        if (a == gridDim.x - 1u) {
            g_barcnt = 0u;
            __threadfence();
            atomicExch(&g_sense, target);
        } else {
            while (*((volatile unsigned*)&g_sense) != target) { __nanosleep(64); }
        }
        __threadfence();
    }
    __syncthreads();
}

// Process one tree level with NT nodes per block-group (R4 scalar matvecs).
template <int NT>
__device__ void do_level(int s0, int cnt,
                         const int* __restrict__ l_tok, const int* __restrict__ l_par,
                         const int* __restrict__ r_tok, const int* __restrict__ r_par,
                         const float* __restrict__ Wiouh, const float* __restrict__ Wfh,
                         float bio0, float bio1, float bio2, float bfh_t,
                         float* s_f, int* s_node, int* s_tok, int* s_parg, int* s_ptok)
{
    const int t = threadIdx.x;
    const int ngrp = (cnt + NT - 1) / NT;

    for (int g = blockIdx.x; g < ngrp; g += gridDim.x) {
        const int base = s0 + g * NT;
        const int nn   = min(NT, cnt - g * NT);
        if (t < NT) {
            int idx  = base + ((t < nn) ? t : 0);    // clamp (dup node 0 of grp)
            int node = g_order[idx];
            int tree = node >> 16, loc = node & (NNODE - 1);
            const int* tokp = tree ? r_tok : l_tok;
            const int* parp = tree ? r_par : l_par;
            int pl = parp[loc];
            s_node[t] = node;
            s_tok[t]  = tokp[loc];
            s_parg[t] = (tree << 16) + pl;
            s_ptok[t] = tokp[pl];
        }
        __syncthreads();
        // load h_sum rows (must bypass L1: updated via L2 atomics)
        #pragma unroll
        for (int n = 0; n < NT; n++)
            s_f[n * M + t] = __ldcg(&g_hsum[s_node[n] * M + t]);
        __syncthreads();

        float a0[NT], a1[NT], a2[NT];
        #pragma unroll
        for (int n = 0; n < NT; n++) {
            int tk = s_tok[n];
            a0[n] = g_ioux[tk * M3 + t]         + bio0;
            a1[n] = g_ioux[tk * M3 + M + t]     + bio1;
            a2[n] = g_ioux[tk * M3 + 2 * M + t] + bio2;
        }

        // ---- Wiouh matvec: explicit two-phase weight double-buffer ----
        {
            float wa0[4], wa1[4], wa2[4], wb0[4], wb1[4], wb2[4];
            #pragma unroll
            for (int kk = 0; kk < 4; kk++) {
                wa0[kk] = Wiouh[kk * M3 + t];
                wa1[kk] = Wiouh[kk * M3 + M + t];
                wa2[kk] = Wiouh[kk * M3 + 2 * M + t];
            }
            #pragma unroll 1
            for (int k = 0; k < M; k += 8) {
                #pragma unroll
                for (int kk = 0; kk < 4; kk++) {
                    wb0[kk] = Wiouh[(k + 4 + kk) * M3 + t];
                    wb1[kk] = Wiouh[(k + 4 + kk) * M3 + M + t];
                    wb2[kk] = Wiouh[(k + 4 + kk) * M3 + 2 * M + t];
                }
                #pragma unroll
                for (int n = 0; n < NT; n++) {
                    const float4 h4 = *reinterpret_cast<const float4*>(s_f + n * M + k);
                    a0[n] += h4.x * wa0[0]; a1[n] += h4.x * wa1[0]; a2[n] += h4.x * wa2[0];
                    a0[n] += h4.y * wa0[1]; a1[n] += h4.y * wa1[1]; a2[n] += h4.y * wa2[1];
                    a0[n] += h4.z * wa0[2]; a1[n] += h4.z * wa1[2]; a2[n] += h4.z * wa2[2];
                    a0[n] += h4.w * wa0[3]; a1[n] += h4.w * wa1[3]; a2[n] += h4.w * wa2[3];
                }
                if (k + 8 < M) {
                    #pragma unroll
                    for (int kk = 0; kk < 4; kk++) {
                        wa0[kk] = Wiouh[(k + 8 + kk) * M3 + t];
                        wa1[kk] = Wiouh[(k + 8 + kk) * M3 + M + t];
                        wa2[kk] = Wiouh[(k + 8 + kk) * M3 + 2 * M + t];
                    }
                }
                #pragma unroll
                for (int n = 0; n < NT; n++) {
                    const float4 h4 = *reinterpret_cast<const float4*>(s_f + n * M + k + 4);
                    a0[n] += h4.x * wb0[0]; a1[n] += h4.x * wb1[0]; a2[n] += h4.x * wb2[0];
                    a0[n] += h4.y * wb0[1]; a1[n] += h4.y * wb1[1]; a2[n] += h4.y * wb2[1];
                    a0[n] += h4.z * wb0[2]; a1[n] += h4.z * wb1[2]; a2[n] += h4.z * wb2[2];
                    a0[n] += h4.w * wb0[3]; a1[n] += h4.w * wb1[3]; a2[n] += h4.w * wb2[3];
                }
            }
        }

        float cv[NT], hv[NT];
        #pragma unroll
        for (int n = 0; n < NT; n++) {
            float fc = __ldcg(&g_fcsum[s_node[n] * M + t]);
            float ig = sigf(a0[n]);
            float og = sigf(a1[n]);
            float ug = tanhf(a2[n]);
            cv[n] = ig * ug + fc;
            hv[n] = og * tanhf(cv[n]);
        }
        __syncthreads();                 // done reading s_f as h_sum
        #pragma unroll
        for (int n = 0; n < NT; n++) s_f[n * M + t] = hv[n];
        __syncthreads();

        float b[NT];
        #pragma unroll
        for (int n = 0; n < NT; n++)
            b[n] = bfh_t + g_fxp[s_ptok[n] * M + t];

        // ---- Wfh matvec: explicit two-phase weight double-buffer ----
        {
            float wa[4], wb[4];
            #pragma unroll
            for (int kk = 0; kk < 4; kk++)
                wa[kk] = Wfh[kk * M + t];
            #pragma unroll 1
            for (int k = 0; k < M; k += 8) {
                #pragma unroll
                for (int kk = 0; kk < 4; kk++)
                    wb[kk] = Wfh[(k + 4 + kk) * M + t];
                #pragma unroll
                for (int n = 0; n < NT; n++) {
                    const float4 h4 = *reinterpret_cast<const float4*>(s_f + n * M + k);
                    b[n] += h4.x * wa[0] + h4.y * wa[1] + h4.z * wa[2] + h4.w * wa[3];
                }
                if (k + 8 < M) {
                    #pragma unroll
                    for (int kk = 0; kk < 4; kk++)
                        wa[kk] = Wfh[(k + 8 + kk) * M + t];
                }
                #pragma unroll
                for (int n = 0; n < NT; n++) {
                    const float4 h4 = *reinterpret_cast<const float4*>(s_f + n * M + k + 4);
                    b[n] += h4.x * wb[0] + h4.y * wb[1] + h4.z * wb[2] + h4.w * wb[3];
                }
            }
        }

        #pragma unroll
        for (int n = 0; n < NT; n++) {
            if (n < nn) {
                int node = s_node[n];
                if (node & (NNODE - 1)) {        // not a root
                    float f = sigf(b[n]);
                    atomicAdd(&g_hsum[s_parg[n] * M + t], hv[n]);
                    atomicAdd(&g_fcsum[s_parg[n] * M + t], f * cv[n]);
                } else {
                    g_croot[(node >> 16) * M + t] = cv[n];
                }
            }
        }
        __syncthreads();
    }
}

extern "C" __global__ void __launch_bounds__(256, 2)
treelstm_kernel(const int* __restrict__ l_tok, const int* __restrict__ l_par,
                const int* __restrict__ r_tok, const int* __restrict__ r_par,
                const float* __restrict__ emb,
                const float* __restrict__ Wioux, const float* __restrict__ bioux,
                const float* __restrict__ Wiouh, const float* __restrict__ biouh,
                const float* __restrict__ Wfx,   const float* __restrict__ bfx,
                const float* __restrict__ Wfh,   const float* __restrict__ bfh,
                const float* __restrict__ Wh,    const float* __restrict__ bh,
                const float* __restrict__ Wp,    const float* __restrict__ bp,
                float* __restrict__ out)
{
    __shared__ __align__(16) float s_f[16 * M];   // 16 KB, multi-purpose
    __shared__ int s_node[16], s_tok[16], s_parg[16], s_ptok[16];

    const int t   = threadIdx.x;
    const int gid = blockIdx.x * blockDim.x + threadIdx.x;
    const int gs  = gridDim.x * blockDim.x;

    // ---------------- Phase 0: zero state + vocab projections ------------
    {
        float4 z4 = make_float4(0.f, 0.f, 0.f, 0.f);
        float4* h4p = reinterpret_cast<float4*>(g_hsum);
        float4* f4p = reinterpret_cast<float4*>(g_fcsum);
        const int n4 = TOT * M / 4;
        for (int i = gid; i < n4; i += gs) h4p[i] = z4;
        for (int i = gid; i < n4; i += gs) f4p[i] = z4;
        for (int i = gid; i < MAXD_CAP; i += gs) g_hist[i] = 0;
        if (gid == 0) g_maxd = 0;

        // vocab projections: groups of VNB vocab rows per block
        const int VG = VOCAB / VNB;   // 125
        for (int g = blockIdx.x; g < VG; g += gridDim.x) {
            #pragma unroll
            for (int n = 0; n < VNB; n++)
                s_f[n * M + t] = emb[(g * VNB + n) * M + t];
            __syncthreads();
            float a0[VNB], a1[VNB], a2[VNB], af[VNB];
            #pragma unroll
            for (int n = 0; n < VNB; n++) {
                a0[n] = bioux[t]; a1[n] = bioux[M + t];
                a2[n] = bioux[2 * M + t]; af[n] = bfx[t];
            }
            #pragma unroll 1
            for (int k = 0; k < M; k += 4) {
                #pragma unroll
                for (int kk = 0; kk < 4; kk++) {
                    float w0 = Wioux[(k + kk) * M3 + t];
                    float w1 = Wioux[(k + kk) * M3 + M + t];
                    float w2 = Wioux[(k + kk) * M3 + 2 * M + t];
                    float wf = Wfx[(k + kk) * M + t];
                    #pragma unroll
                    for (int n = 0; n < VNB; n++) {
                        float xv = s_f[n * M + k + kk];
                        a0[n] += xv * w0; a1[n] += xv * w1;
                        a2[n] += xv * w2; af[n] += xv * wf;
                    }
                }
            }
            #pragma unroll
            for (int n = 0; n < VNB; n++) {
                int v = g * VNB + n;
                g_ioux[v * M3 + t]         = a0[n];
                g_ioux[v * M3 + M + t]     = a1[n];
                g_ioux[v * M3 + 2 * M + t] = a2[n];
                g_fxp[v * M + t]           = af[n];
            }
            __syncthreads();
        }
    }
    gsync();

    // ---------------- Phase 1: depth walk + histogram ---------------------
    for (int i = gid; i < TOT; i += gs) {
        int tree = i >> 16, loc = i & (NNODE - 1);
        const int* parp = tree ? r_par : l_par;
        int d = 0, j = loc;
        while (j) { j = __ldg(parp + j); d++; }
        g_depth[i] = d;
        atomicAdd(&g_hist[d], 1);
        atomicMax(&g_maxd, d);
    }
    gsync();

    // ---------------- Phase 2: serial scan of level offsets --------------
    if (blockIdx.x == 0 && threadIdx.x == 0) {
        int s = 0, md = __ldcg(&g_maxd);
        for (int d = 0; d <= md; d++) {
            g_startv[d] = s; g_cursor[d] = s;
            s += __ldcg(&g_hist[d]);
        }
    }
    gsync();

    // ---------------- Phase 3: scatter nodes into level buckets ----------
    for (int i = gid; i < TOT; i += gs) {
        int d = g_depth[i];
        int pos = atomicAdd(&g_cursor[d], 1);
        g_order[pos] = i;
    }
    gsync();

    // loop-invariant biases
    const float bio0 = biouh[t], bio1 = biouh[M + t], bio2 = biouh[2 * M + t];
    const float bfh_t = bfh[t];

    // ---------------- Phase 4: level loop (deepest first) -----------------
    const int maxd = __ldcg(&g_maxd);
    const int G = gridDim.x;
    for (int d = maxd; d >= 0; --d) {
        const int s0  = __ldcg(&g_startv[d]);
        const int cnt = __ldcg(&g_hist[d]);
        // cost model: waves(NT) * (NT + 3); +3 charges fixed weight-stream cost
        const long c16 = (long)(((cnt + 15) / 16 + G - 1) / G) * 19;
        const long c8  = (long)(((cnt + 7) / 8 + G - 1) / G) * 11;
        const long c4  = (long)(((cnt + 3) / 4 + G - 1) / G) * 7;
        if (c16 <= c8 && c16 <= c4)
            do_level<16>(s0, cnt, l_tok, l_par, r_tok, r_par, Wiouh, Wfh,
                         bio0, bio1, bio2, bfh_t, s_f, s_node, s_tok, s_parg, s_ptok);
        else if (c8 <= c4)
            do_level<8>(s0, cnt, l_tok, l_par, r_tok, r_par, Wiouh, Wfh,
                        bio0, bio1, bio2, bfh_t, s_f, s_node, s_tok, s_parg, s_ptok);
        else
            do_level<4>(s0, cnt, l_tok, l_par, r_tok, r_par, Wiouh, Wfh,
                        bio0, bio1, bio2, bfh_t, s_f, s_node, s_tok, s_parg, s_ptok);
        gsync();
    }

    // ---------------- Phase 5: similarity head (block 0) ------------------
    if (blockIdx.x == 0) {
        float cl = __ldcg(&g_croot[t]);
        float cr = __ldcg(&g_croot[M + t]);
        s_f[t]     = cl * cr;
        s_f[M + t] = fabsf(cl - cr);
        __syncthreads();
        float acc = bh[t];
        for (int k = 0; k < 2 * M; k++) acc += s_f[k] * Wh[k * M + t];
        float hid = sigf(acc);
        s_f[2 * M + t] = hid * Wp[2 * t];
        s_f[3 * M + t] = hid * Wp[2 * t + 1];
        __syncthreads();
        if (t == 0) {
            float l0 = bp[0], l1 = bp[1];
            for (int k = 0; k < M; k++) { l0 += s_f[2 * M + k]; l1 += s_f[3 * M + k]; }
            float mx = fmaxf(l0, l1);
            float e0 = expf(l0 - mx), e1 = expf(l1 - mx);
            float inv = 1.0f / (e0 + e1);
            out[0] = e0 * inv;
            out[1] = e1 * inv;
        }
    }
}

extern "C" void kernel_launch(void* const* d_in, const int* in_sizes, int n_in,
                              void* d_out, int out_size)
{
    (void)in_sizes; (void)n_in; (void)out_size;
    int dev = 0;
    cudaGetDevice(&dev);
    int nsm = 0;
    cudaDeviceGetAttribute(&nsm, cudaDevAttrMultiProcessorCount, dev);
    if (nsm <= 0) nsm = 148;

    treelstm_kernel<<<2 * nsm, 256>>>(
        (const int*)d_in[0], (const int*)d_in[1],
        (const int*)d_in[2], (const int*)d_in[3],
        (const float*)d_in[4],
        (const float*)d_in[5], (const float*)d_in[6],
        (const float*)d_in[7], (const float*)d_in[8],
        (const float*)d_in[9], (const float*)d_in[10],
        (const float*)d_in[11], (const float*)d_in[12],
        (const float*)d_in[13], (const float*)d_in[14],
        (const float*)d_in[15], (const float*)d_in[16],
        (float*)d_out);
}

// round 8
// speedup vs baseline: 2.9477x; 1.4356x over previous
#include <cuda_runtime.h>
#include <math.h>

// SimilarityTreeLSTM on GB300: level-parallel tree evaluation in one
// persistent kernel with a software grid barrier.
//
// R7 changes vs R6 (2760us):
//  * LEAF ELIMINATION: ~50% of nodes are leaves (random recursive tree);
//    leaf h/c depend only on the token -> per-vocab tables h_leaf/c_leaf
//    and hfW = h_leaf@Wfh + bfh. Leaves become a bulk coalesced atomic
//    scatter; only internal nodes (~half) run the 262K-MAC matvec path.
//    FMA floor drops 1.96ms -> 0.98ms.
//  * keeps R6 adaptive NT {16,8,4} for internal levels.

#define NNODE 65536
#define TOT   (2 * NNODE)
#define M     256
#define M3    (3 * M)
#define VOCAB 1000
#define VNB   8
#define MAXD_CAP 65536

// ---------------- device scratch (static: no allocations allowed) ----------
__device__ float g_hsum[TOT * M];        // 134 MB
__device__ float g_fcsum[TOT * M];       // 134 MB
__device__ float g_ioux[VOCAB * M3];     // vocab proj: emb@Wioux + bioux
__device__ float g_fxp[VOCAB * M];       // vocab proj: emb@Wfx + bfx
__device__ float g_hleaf[VOCAB * M];     // leaf h by token
__device__ float g_cleaf[VOCAB * M];     // leaf c by token
__device__ float g_hfw[VOCAB * M];       // h_leaf @ Wfh + bfh
__device__ int   g_nchild[TOT];
__device__ int   g_depth[TOT];
__device__ int   g_order[TOT];           // internal nodes by level
__device__ int   g_leaf[TOT];            // leaf nodes
__device__ int   g_nleaf;
__device__ int   g_hist[MAXD_CAP];
__device__ int   g_startv[MAXD_CAP];
__device__ int   g_cursor[MAXD_CAP];
__device__ int   g_maxd;
__device__ float g_croot[2 * M];
__device__ unsigned g_barcnt;
__device__ unsigned g_sense;

__device__ __forceinline__ float sigf(float x) {
    return 1.0f / (1.0f + expf(-x));
}

// Sense-reversal grid barrier. Requires all blocks co-resident.
__device__ __forceinline__ void gsync() {
    __syncthreads();
    if (threadIdx.x == 0) {
        __threadfence();
        unsigned target = *((volatile unsigned*)&g_sense) + 1u;
        unsigned a = atomicAdd(&g_barcnt, 1u);
        if (a == gridDim.x - 1u) {
            g_barcnt = 0u;
            __threadfence();
            atomicExch(&g_sense, target);
        } else {
            while (*((volatile unsigned*)&g_sense) != target) { __nanosleep(64); }
        }
        __threadfence();
    }
    __syncthreads();
}

// Process one internal-node level with NT nodes per block-group.
template <int NT>
__device__ void do_level(int s0, int cnt,
                         const int* __restrict__ l_tok, const int* __restrict__ l_par,
                         const int* __restrict__ r_tok, const int* __restrict__ r_par,
                         const float* __restrict__ Wiouh, const float* __restrict__ Wfh,
                         float bio0, float bio1, float bio2, float bfh_t,
                         float* s_f, int* s_node, int* s_tok, int* s_parg, int* s_ptok)
{
    const int t = threadIdx.x;
    const int ngrp = (cnt + NT - 1) / NT;

    for (int g = blockIdx.x; g < ngrp; g += gridDim.x) {
        const int base = s0 + g * NT;
        const int nn   = min(NT, cnt - g * NT);
        if (t < NT) {
            int idx  = base + ((t < nn) ? t : 0);    // clamp (dup node 0 of grp)
            int node = g_order[idx];
            int tree = node >> 16, loc = node & (NNODE - 1);
            const int* tokp = tree ? r_tok : l_tok;
            const int* parp = tree ? r_par : l_par;
            int pl = parp[loc];
            s_node[t] = node;
            s_tok[t]  = tokp[loc];
            s_parg[t] = (tree << 16) + pl;
            s_ptok[t] = tokp[pl];
        }
        __syncthreads();
        // load h_sum rows (must bypass L1: updated via L2 atomics)
        #pragma unroll
        for (int n = 0; n < NT; n++)
            s_f[n * M + t] = __ldcg(&g_hsum[s_node[n] * M + t]);
        __syncthreads();

        float a0[NT], a1[NT], a2[NT];
        #pragma unroll
        for (int n = 0; n < NT; n++) {
            int tk = s_tok[n];
            a0[n] = g_ioux[tk * M3 + t]         + bio0;
            a1[n] = g_ioux[tk * M3 + M + t]     + bio1;
            a2[n] = g_ioux[tk * M3 + 2 * M + t] + bio2;
        }

        // ---- Wiouh matvec: explicit two-phase weight double-buffer ----
        {
            float wa0[4], wa1[4], wa2[4], wb0[4], wb1[4], wb2[4];
            #pragma unroll
            for (int kk = 0; kk < 4; kk++) {
                wa0[kk] = Wiouh[kk * M3 + t];
                wa1[kk] = Wiouh[kk * M3 + M + t];
                wa2[kk] = Wiouh[kk * M3 + 2 * M + t];
            }
            #pragma unroll 1
            for (int k = 0; k < M; k += 8) {
                #pragma unroll
                for (int kk = 0; kk < 4; kk++) {
                    wb0[kk] = Wiouh[(k + 4 + kk) * M3 + t];
                    wb1[kk] = Wiouh[(k + 4 + kk) * M3 + M + t];
                    wb2[kk] = Wiouh[(k + 4 + kk) * M3 + 2 * M + t];
                }
                #pragma unroll
                for (int n = 0; n < NT; n++) {
                    const float4 h4 = *reinterpret_cast<const float4*>(s_f + n * M + k);
                    a0[n] += h4.x * wa0[0]; a1[n] += h4.x * wa1[0]; a2[n] += h4.x * wa2[0];
                    a0[n] += h4.y * wa0[1]; a1[n] += h4.y * wa1[1]; a2[n] += h4.y * wa2[1];
                    a0[n] += h4.z * wa0[2]; a1[n] += h4.z * wa1[2]; a2[n] += h4.z * wa2[2];
                    a0[n] += h4.w * wa0[3]; a1[n] += h4.w * wa1[3]; a2[n] += h4.w * wa2[3];
                }
                if (k + 8 < M) {
                    #pragma unroll
                    for (int kk = 0; kk < 4; kk++) {
                        wa0[kk] = Wiouh[(k + 8 + kk) * M3 + t];
                        wa1[kk] = Wiouh[(k + 8 + kk) * M3 + M + t];
                        wa2[kk] = Wiouh[(k + 8 + kk) * M3 + 2 * M + t];
                    }
                }
                #pragma unroll
                for (int n = 0; n < NT; n++) {
                    const float4 h4 = *reinterpret_cast<const float4*>(s_f + n * M + k + 4);
                    a0[n] += h4.x * wb0[0]; a1[n] += h4.x * wb1[0]; a2[n] += h4.x * wb2[0];
                    a0[n] += h4.y * wb0[1]; a1[n] += h4.y * wb1[1]; a2[n] += h4.y * wb2[1];
                    a0[n] += h4.z * wb0[2]; a1[n] += h4.z * wb1[2]; a2[n] += h4.z * wb2[2];
                    a0[n] += h4.w * wb0[3]; a1[n] += h4.w * wb1[3]; a2[n] += h4.w * wb2[3];
                }
            }
        }

        float cv[NT], hv[NT];
        #pragma unroll
        for (int n = 0; n < NT; n++) {
            float fc = __ldcg(&g_fcsum[s_node[n] * M + t]);
            float ig = sigf(a0[n]);
            float og = sigf(a1[n]);
            float ug = tanhf(a2[n]);
            cv[n] = ig * ug + fc;
            hv[n] = og * tanhf(cv[n]);
        }
        __syncthreads();                 // done reading s_f as h_sum
        #pragma unroll
        for (int n = 0; n < NT; n++) s_f[n * M + t] = hv[n];
        __syncthreads();

        float b[NT];
        #pragma unroll
        for (int n = 0; n < NT; n++)
            b[n] = bfh_t + g_fxp[s_ptok[n] * M + t];

        // ---- Wfh matvec: explicit two-phase weight double-buffer ----
        {
            float wa[4], wb[4];
            #pragma unroll
            for (int kk = 0; kk < 4; kk++)
                wa[kk] = Wfh[kk * M + t];
            #pragma unroll 1
            for (int k = 0; k < M; k += 8) {
                #pragma unroll
                for (int kk = 0; kk < 4; kk++)
                    wb[kk] = Wfh[(k + 4 + kk) * M + t];
                #pragma unroll
                for (int n = 0; n < NT; n++) {
                    const float4 h4 = *reinterpret_cast<const float4*>(s_f + n * M + k);
                    b[n] += h4.x * wa[0] + h4.y * wa[1] + h4.z * wa[2] + h4.w * wa[3];
                }
                if (k + 8 < M) {
                    #pragma unroll
                    for (int kk = 0; kk < 4; kk++)
                        wa[kk] = Wfh[(k + 8 + kk) * M + t];
                }
                #pragma unroll
                for (int n = 0; n < NT; n++) {
                    const float4 h4 = *reinterpret_cast<const float4*>(s_f + n * M + k + 4);
                    b[n] += h4.x * wb[0] + h4.y * wb[1] + h4.z * wb[2] + h4.w * wb[3];
                }
            }
        }

        #pragma unroll
        for (int n = 0; n < NT; n++) {
            if (n < nn) {
                int node = s_node[n];
                if (node & (NNODE - 1)) {        // not a root
                    float f = sigf(b[n]);
                    atomicAdd(&g_hsum[s_parg[n] * M + t], hv[n]);
                    atomicAdd(&g_fcsum[s_parg[n] * M + t], f * cv[n]);
                } else {
                    g_croot[(node >> 16) * M + t] = cv[n];
                }
            }
        }
        __syncthreads();
    }
}

extern "C" __global__ void __launch_bounds__(256, 2)
treelstm_kernel(const int* __restrict__ l_tok, const int* __restrict__ l_par,
                const int* __restrict__ r_tok, const int* __restrict__ r_par,
                const float* __restrict__ emb,
                const float* __restrict__ Wioux, const float* __restrict__ bioux,
                const float* __restrict__ Wiouh, const float* __restrict__ biouh,
                const float* __restrict__ Wfx,   const float* __restrict__ bfx,
                const float* __restrict__ Wfh,   const float* __restrict__ bfh,
                const float* __restrict__ Wh,    const float* __restrict__ bh,
                const float* __restrict__ Wp,    const float* __restrict__ bp,
                float* __restrict__ out)
{
    __shared__ __align__(16) float s_f[16 * M];   // 16 KB, multi-purpose
    __shared__ int s_node[16], s_tok[16], s_parg[16], s_ptok[16];

    const int t   = threadIdx.x;
    const int gid = blockIdx.x * blockDim.x + threadIdx.x;
    const int gs  = gridDim.x * blockDim.x;

    // ---------------- Phase 0: zero state + vocab projections ------------
    {
        float4 z4 = make_float4(0.f, 0.f, 0.f, 0.f);
        float4* h4p = reinterpret_cast<float4*>(g_hsum);
        float4* f4p = reinterpret_cast<float4*>(g_fcsum);
        const int n4 = TOT * M / 4;
        for (int i = gid; i < n4; i += gs) h4p[i] = z4;
        for (int i = gid; i < n4; i += gs) f4p[i] = z4;
        for (int i = gid; i < MAXD_CAP; i += gs) g_hist[i] = 0;
        for (int i = gid; i < TOT; i += gs) g_nchild[i] = 0;
        if (gid == 0) { g_maxd = 0; g_nleaf = 0; }

        // vocab projections: groups of VNB vocab rows per block
        const int VG = VOCAB / VNB;   // 125
        for (int g = blockIdx.x; g < VG; g += gridDim.x) {
            #pragma unroll
            for (int n = 0; n < VNB; n++)
                s_f[n * M + t] = emb[(g * VNB + n) * M + t];
            __syncthreads();
            float a0[VNB], a1[VNB], a2[VNB], af[VNB];
            #pragma unroll
            for (int n = 0; n < VNB; n++) {
                a0[n] = bioux[t]; a1[n] = bioux[M + t];
                a2[n] = bioux[2 * M + t]; af[n] = bfx[t];
            }
            #pragma unroll 1
            for (int k = 0; k < M; k += 4) {
                #pragma unroll
                for (int kk = 0; kk < 4; kk++) {
                    float w0 = Wioux[(k + kk) * M3 + t];
                    float w1 = Wioux[(k + kk) * M3 + M + t];
                    float w2 = Wioux[(k + kk) * M3 + 2 * M + t];
                    float wf = Wfx[(k + kk) * M + t];
                    #pragma unroll
                    for (int n = 0; n < VNB; n++) {
                        float xv = s_f[n * M + k + kk];
                        a0[n] += xv * w0; a1[n] += xv * w1;
                        a2[n] += xv * w2; af[n] += xv * wf;
                    }
                }
            }
            #pragma unroll
            for (int n = 0; n < VNB; n++) {
                int v = g * VNB + n;
                g_ioux[v * M3 + t]         = a0[n];
                g_ioux[v * M3 + M + t]     = a1[n];
                g_ioux[v * M3 + 2 * M + t] = a2[n];
                g_fxp[v * M + t]           = af[n];
            }
            __syncthreads();
        }
    }
    gsync();

    // loop-invariant biases
    const float bio0 = biouh[t], bio1 = biouh[M + t], bio2 = biouh[2 * M + t];
    const float bfh_t = bfh[t];

    // ---------------- Phase 1: depth walk + child counts ------------------
    for (int i = gid; i < TOT; i += gs) {
        int tree = i >> 16, loc = i & (NNODE - 1);
        const int* parp = tree ? r_par : l_par;
        int d = 0, j = loc;
        while (j) { j = __ldg(parp + j); d++; }
        g_depth[i] = d;
        if (loc) {
            int pg = (tree << 16) + __ldg(parp + loc);
            atomicAdd(&g_nchild[pg], 1);
        }
    }
    gsync();

    // ---------------- Phase 1b: internal-node histogram + leaf tables ----
    for (int i = gid; i < TOT; i += gs) {
        if (__ldcg(&g_nchild[i]) > 0) {
            int d = g_depth[i];
            atomicAdd(&g_hist[d], 1);
            atomicMax(&g_maxd, d);
        }
    }
    // leaf h/c tables: elementwise over VOCAB x M
    for (int i = gid; i < VOCAB * M; i += gs) {
        int v = i / M, e = i % M;
        float i0 = g_ioux[v * M3 + e]         + biouh[e];
        float i1 = g_ioux[v * M3 + M + e]     + biouh[M + e];
        float i2 = g_ioux[v * M3 + 2 * M + e] + biouh[2 * M + e];
        float c  = sigf(i0) * tanhf(i2);
        g_cleaf[i] = c;
        g_hleaf[i] = sigf(i1) * tanhf(c);
    }
    gsync();

    // ---------------- Phase 2: serial scan of level offsets --------------
    if (blockIdx.x == 0 && threadIdx.x == 0) {
        int s = 0, md = __ldcg(&g_maxd);
        for (int d = 0; d <= md; d++) {
            g_startv[d] = s; g_cursor[d] = s;
            s += __ldcg(&g_hist[d]);
        }
    }
    gsync();

    // ------- Phase 3: scatter nodes into buckets; hfW = h_leaf@Wfh + bfh --
    for (int i = gid; i < TOT; i += gs) {
        if (__ldcg(&g_nchild[i]) > 0) {
            int d = g_depth[i];
            int pos = atomicAdd(&g_cursor[d], 1);
            g_order[pos] = i;
        } else {
            int pos = atomicAdd(&g_nleaf, 1);
            g_leaf[pos] = i;
        }
    }
    {
        const int VG = VOCAB / VNB;   // 125
        for (int g = blockIdx.x; g < VG; g += gridDim.x) {
            #pragma unroll
            for (int n = 0; n < VNB; n++)
                s_f[n * M + t] = g_hleaf[(g * VNB + n) * M + t];
            __syncthreads();
            float b[VNB];
            #pragma unroll
            for (int n = 0; n < VNB; n++) b[n] = bfh_t;
            #pragma unroll 1
            for (int k = 0; k < M; k += 4) {
                #pragma unroll
                for (int kk = 0; kk < 4; kk++) {
                    float w = Wfh[(k + kk) * M + t];
                    #pragma unroll
                    for (int n = 0; n < VNB; n++)
                        b[n] += s_f[n * M + k + kk] * w;
                }
            }
            #pragma unroll
            for (int n = 0; n < VNB; n++)
                g_hfw[(g * VNB + n) * M + t] = b[n];
            __syncthreads();
        }
    }
    gsync();

    // ---------------- Phase 4L: bulk leaf scatter --------------------------
    {
        const int nleaf = __ldcg(&g_nleaf);
        const int ngrp = (nleaf + 7) / 8;
        for (int g = blockIdx.x; g < ngrp; g += gridDim.x) {
            const int base = g * 8;
            const int nn = min(8, nleaf - base);
            if (t < 8) {
                int node = g_leaf[base + ((t < nn) ? t : 0)];
                int tree = node >> 16, loc = node & (NNODE - 1);
                const int* tokp = tree ? r_tok : l_tok;
                const int* parp = tree ? r_par : l_par;
                int pl = parp[loc];
                s_node[t] = node;
                s_tok[t]  = tokp[loc];
                s_parg[t] = (tree << 16) + pl;
                s_ptok[t] = tokp[pl];
            }
            __syncthreads();
            #pragma unroll
            for (int n = 0; n < 8; n++) {
                if (n < nn) {
                    int v  = s_tok[n];
                    int pg = s_parg[n];
                    int pv = s_ptok[n];
                    float hl = g_hleaf[v * M + t];
                    float cl = g_cleaf[v * M + t];
                    float f  = sigf(g_hfw[v * M + t] + g_fxp[pv * M + t]);
                    atomicAdd(&g_hsum[pg * M + t], hl);
                    atomicAdd(&g_fcsum[pg * M + t], f * cl);
                }
            }
            __syncthreads();
        }
    }
    gsync();

    // ---------------- Phase 4: internal level loop (deepest first) --------
    const int maxd = __ldcg(&g_maxd);
    const int G = gridDim.x;
    for (int d = maxd; d >= 0; --d) {
        const int s0  = __ldcg(&g_startv[d]);
        const int cnt = __ldcg(&g_hist[d]);
        // cost model: waves(NT) * (NT + 3); +3 charges fixed weight-stream cost
        const long c16 = (long)(((cnt + 15) / 16 + G - 1) / G) * 19;
        const long c8  = (long)(((cnt + 7) / 8 + G - 1) / G) * 11;
        const long c4  = (long)(((cnt + 3) / 4 + G - 1) / G) * 7;
        if (c16 <= c8 && c16 <= c4)
            do_level<16>(s0, cnt, l_tok, l_par, r_tok, r_par, Wiouh, Wfh,
                         bio0, bio1, bio2, bfh_t, s_f, s_node, s_tok, s_parg, s_ptok);
        else if (c8 <= c4)
            do_level<8>(s0, cnt, l_tok, l_par, r_tok, r_par, Wiouh, Wfh,
                        bio0, bio1, bio2, bfh_t, s_f, s_node, s_tok, s_parg, s_ptok);
        else
            do_level<4>(s0, cnt, l_tok, l_par, r_tok, r_par, Wiouh, Wfh,
                        bio0, bio1, bio2, bfh_t, s_f, s_node, s_tok, s_parg, s_ptok);
        gsync();
    }

    // ---------------- Phase 5: similarity head (block 0) ------------------
    if (blockIdx.x == 0) {
        float cl = __ldcg(&g_croot[t]);
        float cr = __ldcg(&g_croot[M + t]);
        s_f[t]     = cl * cr;
        s_f[M + t] = fabsf(cl - cr);
        __syncthreads();
        float acc = bh[t];
        for (int k = 0; k < 2 * M; k++) acc += s_f[k] * Wh[k * M + t];
        float hid = sigf(acc);
        s_f[2 * M + t] = hid * Wp[2 * t];
        s_f[3 * M + t] = hid * Wp[2 * t + 1];
        __syncthreads();
        if (t == 0) {
            float l0 = bp[0], l1 = bp[1];
            for (int k = 0; k < M; k++) { l0 += s_f[2 * M + k]; l1 += s_f[3 * M + k]; }
            float mx = fmaxf(l0, l1);
            float e0 = expf(l0 - mx), e1 = expf(l1 - mx);
            float inv = 1.0f / (e0 + e1);
            out[0] = e0 * inv;
            out[1] = e1 * inv;
        }
    }
}

extern "C" void kernel_launch(void* const* d_in, const int* in_sizes, int n_in,
                              void* d_out, int out_size)
{
    (void)in_sizes; (void)n_in; (void)out_size;
    int dev = 0;
    cudaGetDevice(&dev);
    int nsm = 0;
    cudaDeviceGetAttribute(&nsm, cudaDevAttrMultiProcessorCount, dev);
    if (nsm <= 0) nsm = 148;

    treelstm_kernel<<<2 * nsm, 256>>>(
        (const int*)d_in[0], (const int*)d_in[1],
        (const int*)d_in[2], (const int*)d_in[3],
        (const float*)d_in[4],
        (const float*)d_in[5], (const float*)d_in[6],
        (const float*)d_in[7], (const float*)d_in[8],
        (const float*)d_in[9], (const float*)d_in[10],
        (const float*)d_in[11], (const float*)d_in[12],
        (const float*)d_in[13], (const float*)d_in[14],
        (const float*)d_in[15], (const float*)d_in[16],
        (float*)d_out);
}